// round 1
// baseline (speedup 1.0000x reference)
#include <cuda_runtime.h>
#include <math.h>

#define BB 4
#define CC 64
#define OO 64
#define HH 128
#define WW 128
#define HW (HH*WW)
#define K2 9
#define CK (CC*K2)   // 576

// Scratch: offset-conv output. Channels 0..8 = off_x, 9..17 = off_y, 18..26 = sigmoid(mask).
__device__ float g_om[BB * 27 * HW];

// ---------------------------------------------------------------------------
// Kernel A: 3x3 conv over feat -> 27 channels (off_x, off_y, mask-logit),
// bias added, mask sigmoided, written to g_om.
// One thread per output pixel, 27(+1 pad) register accumulators.
// Weights staged in SMEM as [c_local*9+kk][28] so inner loop is 7x LDS.128
// broadcast + 28 FMA per (c,ky,kx).
// ---------------------------------------------------------------------------
__global__ __launch_bounds__(128) void off_conv_kernel(
    const float* __restrict__ feat,
    const float* __restrict__ w_off,
    const float* __restrict__ b_off)
{
    __shared__ float sw[288 * 28];   // 32 channels * 9 taps, oc padded 27->28 (31.5 KB)

    const int b   = blockIdx.y;
    const int pix = blockIdx.x * 128 + threadIdx.x;
    const int y   = pix >> 7;
    const int x   = pix & 127;

    float acc[28];
#pragma unroll
    for (int i = 0; i < 28; i++) acc[i] = 0.f;

    const float* fb = feat + (size_t)b * CC * HW;

    for (int cc = 0; cc < 2; cc++) {          // channel chunks of 32
        __syncthreads();
        for (int i = threadIdx.x; i < 288 * 28; i += 128) {
            int oc = i % 28;
            int ck = i / 28;                  // (c_local*9 + kk)
            sw[i] = (oc < 27) ? w_off[oc * CK + cc * 288 + ck] : 0.f;
        }
        __syncthreads();

        for (int cl = 0; cl < 32; cl++) {
            const float* fp = fb + (size_t)(cc * 32 + cl) * HW;
#pragma unroll
            for (int ky = 0; ky < 3; ky++) {
                const int yy  = y + ky - 1;
                const bool yok = ((unsigned)yy < HH);
#pragma unroll
                for (int kx = 0; kx < 3; kx++) {
                    const int xx = x + kx - 1;
                    float v = (yok && (unsigned)xx < WW) ? __ldg(fp + yy * WW + xx) : 0.f;
                    const float4* w4 = (const float4*)(sw + (cl * 9 + ky * 3 + kx) * 28);
#pragma unroll
                    for (int j = 0; j < 7; j++) {
                        float4 wv = w4[j];
                        acc[j * 4 + 0] += v * wv.x;
                        acc[j * 4 + 1] += v * wv.y;
                        acc[j * 4 + 2] += v * wv.z;
                        acc[j * 4 + 3] += v * wv.w;
                    }
                }
            }
        }
    }

    float* omb = g_om + (size_t)b * 27 * HW;
#pragma unroll
    for (int oc = 0; oc < 27; oc++) {
        float z = acc[oc] + __ldg(b_off + oc);
        if (oc >= 18) z = 1.f / (1.f + expf(-z));   // sigmoid for mask channels
        omb[oc * HW + pix] = z;
    }
}

// ---------------------------------------------------------------------------
// Kernel B: fused modulated deformable sampling + (O x C*K2) GEMM + bias + relu.
// One thread per output pixel, 64 output accumulators in registers.
// Per tap: bilinear weights computed once (mask + validity folded into the 4
// corner weights), then per channel: 4 gathered loads of x (L1/L2-resident),
// 16x LDS.128 broadcast weight reads, 64 FMAs.
// ---------------------------------------------------------------------------
__global__ __launch_bounds__(128) void deform_kernel(
    const float* __restrict__ x,
    const float* __restrict__ w_def,
    const float* __restrict__ b_def,
    float* __restrict__ out)
{
    __shared__ float sw[CC * OO];   // [c][o], 16 KB, reloaded per tap

    const int bidx = blockIdx.x;
    const int b  = bidx >> 7;       // / HH
    const int y  = bidx & 127;
    const int xo = threadIdx.x;
    const int pix = y * WW + xo;

    float acc[OO];
#pragma unroll
    for (int i = 0; i < OO; i++) acc[i] = 0.f;

    const float* xb  = x + (size_t)b * CC * HW;
    const float* omb = g_om + (size_t)b * 27 * HW;

    for (int tap = 0; tap < 9; tap++) {
        __syncthreads();
        for (int i = threadIdx.x; i < CC * OO; i += 128) {
            int c = i >> 6, o = i & 63;
            sw[i] = w_def[o * CK + c * K2 + tap];
        }
        __syncthreads();

        const float offx = omb[(tap)      * HW + pix];
        const float offy = omb[(9  + tap) * HW + pix];
        const float m    = omb[(18 + tap) * HW + pix];

        const int dy = tap / 3 - 1;
        const int dx = tap % 3 - 1;
        const float ys = (float)(y  + dy) + offy;
        const float xs = (float)(xo + dx) + offx;

        const float y0f = floorf(ys), x0f = floorf(xs);
        const float wy1 = ys - y0f,  wx1 = xs - x0f;
        const float wy0 = 1.f - wy1, wx0 = 1.f - wx1;

        const int iy0 = (int)y0f, ix0 = (int)x0f;
        const int iy1 = iy0 + 1,  ix1 = ix0 + 1;
        const bool vy0 = ((unsigned)iy0 < HH), vy1 = ((unsigned)iy1 < HH);
        const bool vx0 = ((unsigned)ix0 < WW), vx1 = ((unsigned)ix1 < WW);

        const float w00 = (vy0 && vx0) ? wy0 * wx0 * m : 0.f;
        const float w01 = (vy0 && vx1) ? wy0 * wx1 * m : 0.f;
        const float w10 = (vy1 && vx0) ? wy1 * wx0 * m : 0.f;
        const float w11 = (vy1 && vx1) ? wy1 * wx1 * m : 0.f;

        const int cy0 = min(max(iy0, 0), HH - 1), cy1 = min(max(iy1, 0), HH - 1);
        const int cx0 = min(max(ix0, 0), WW - 1), cx1 = min(max(ix1, 0), WW - 1);
        const int i00 = cy0 * WW + cx0, i01 = cy0 * WW + cx1;
        const int i10 = cy1 * WW + cx0, i11 = cy1 * WW + cx1;

        const float4* swv = (const float4*)sw;
#pragma unroll 2
        for (int c = 0; c < CC; c++) {
            const float* xp = xb + (size_t)c * HW;
            float v = w00 * __ldg(xp + i00) + w01 * __ldg(xp + i01)
                    + w10 * __ldg(xp + i10) + w11 * __ldg(xp + i11);
#pragma unroll
            for (int j = 0; j < 16; j++) {
                float4 wv = swv[c * 16 + j];
                acc[j * 4 + 0] += v * wv.x;
                acc[j * 4 + 1] += v * wv.y;
                acc[j * 4 + 2] += v * wv.z;
                acc[j * 4 + 3] += v * wv.w;
            }
        }
    }

    float* ob = out + (size_t)b * OO * HW;
#pragma unroll
    for (int o = 0; o < OO; o++) {
        float z = acc[o] + __ldg(b_def + o);
        ob[o * HW + pix] = fmaxf(z, 0.f);
    }
}

extern "C" void kernel_launch(void* const* d_in, const int* in_sizes, int n_in,
                              void* d_out, int out_size) {
    const float* x     = (const float*)d_in[0];
    const float* feat  = (const float*)d_in[1];
    const float* w_off = (const float*)d_in[2];
    const float* b_off = (const float*)d_in[3];
    const float* w_def = (const float*)d_in[4];
    const float* b_def = (const float*)d_in[5];
    float* out = (float*)d_out;

    dim3 gA(HW / 128, BB);
    off_conv_kernel<<<gA, 128>>>(feat, w_off, b_off);
    deform_kernel<<<BB * HH, 128>>>(x, w_def, b_def, out);
}